// round 14
// baseline (speedup 1.0000x reference)
#include <cuda_runtime.h>
#include <cuda_bf16.h>

#define ROWS 4096
#define COLS 32000
#define NF4  (COLS / 4)              // 8000 float4 per row
#define SEGS 4
#define SEGQ (NF4 / SEGS)            // 2000 float4 per K1 segment
#define CAP  3072                    // compacted capacity (expected ~730 kept)
#define PAD  9216                    // smem pad: 36KB -> 6 CTAs/SM (L2 fit)
#define BD   256
#define NEG_INF (-3.402823466e38f)

__device__ unsigned g_maxu[ROWS];

// Monotone float<->uint mapping for atomicMax on floats (any sign).
__device__ __forceinline__ unsigned fenc(float f) {
    unsigned b = __float_as_uint(f);
    return b ^ ((unsigned)((int)b >> 31) | 0x80000000u);
}
__device__ __forceinline__ float fdec(unsigned u) {
    unsigned b = u ^ ((u & 0x80000000u) ? 0x80000000u : 0xFFFFFFFFu);
    return __uint_as_float(b);
}

// K0: reset per-row max (graph replays => must re-init every launch).
// 0 is a safe identity: fenc(x) >= 0x00800000 > 0 for any finite float.
__global__ void k0_init() {
    g_maxu[blockIdx.x * BD + threadIdx.x] = 0u;
}

// ===========================================================================
// K1: row max, 4 segment-CTAs per row. Pure load+fmax streaming, warp reduce,
// one global atomicMax per warp. No smem, no block sync.
// ===========================================================================
__global__ __launch_bounds__(BD, 8) void k1_rowmax(const float* __restrict__ X) {
    const int b   = blockIdx.x;
    const int row = b >> 2;
    const int seg = b & 3;
    const float4* Xr = reinterpret_cast<const float4*>(X + (size_t)row * COLS) + seg * SEGQ;

    float m = NEG_INF;
    for (int i = threadIdx.x; i < SEGQ; i += BD) {
        float4 v = Xr[i];
        m = fmaxf(m, fmaxf(fmaxf(v.x, v.y), fmaxf(v.z, v.w)));
    }
    #pragma unroll
    for (int o = 16; o > 0; o >>= 1)
        m = fmaxf(m, __shfl_xor_sync(0xFFFFFFFFu, m, o));
    if ((threadIdx.x & 31) == 0)
        atomicMax(&g_maxu[row], fenc(m));
}

// ===========================================================================
// K2: one CTA (256 thr) per row. R2-equivalent structure:
//   Phase A: read row, ballot-compact xs > (max_s - 1) into smem.
//            (8000 = 31*256 + 64: the last iteration contains exactly warps
//             0 and 1 complete, so full-mask ballots stay legal.)
//   Phase B: warp 0 runs the 50-iter bisection (identical recursion).
//   Phase C: re-read row (L2-hot: 6 CTAs/SM => resident set fits L2) and
//            write full quads with __stcs (don't evict X lines).
// ===========================================================================
__global__ __launch_bounds__(BD, 6) void k2_entmax(const float* __restrict__ X,
                                                   float* __restrict__ out) {
    const int row = blockIdx.x;
    const float4* Xr = reinterpret_cast<const float4*>(X + (size_t)row * COLS);
    float4* Or = reinterpret_cast<float4*>(out + (size_t)row * COLS);

    __shared__ float s_vals[PAD];    // only first CAP used; rest pads occupancy
    __shared__ int   s_count;
    __shared__ float s_tau, s_invZ;

    const int tid  = threadIdx.x;
    const int lane = tid & 31;
    const int wrp  = tid >> 5;

    if (tid == 0) s_count = 0;
    __syncthreads();

    const float max_s  = fdec(g_maxu[row]) * 0.5f;   // exact max * (alpha-1)
    const float thresh = max_s - 1.0f;               // initial tau_lo

    // ---- Phase A: compact support superset (ballot-aggregated)
    for (int i = tid; i < NF4; i += BD) {
        float4 v = Xr[i];
        const float xs[4] = {v.x * 0.5f, v.y * 0.5f, v.z * 0.5f, v.w * 0.5f};
        #pragma unroll
        for (int k = 0; k < 4; k++) {
            const bool p = (xs[k] > thresh);
            const unsigned mask = __ballot_sync(0xFFFFFFFFu, p);
            if (mask == 0u) continue;
            if (p) {
                const int rank   = __popc(mask & ((1u << lane) - 1u));
                const int leader = __ffs(mask) - 1;
                int base = 0;
                if (lane == leader) base = atomicAdd(&s_count, __popc(mask));
                base = __shfl_sync(mask, base, leader);
                const int idx = base + rank;
                if (idx < CAP) s_vals[idx] = xs[k];
            }
        }
    }
    __syncthreads();

    const int  cnt = s_count;
    const int  n   = (cnt < CAP) ? cnt : CAP;
    const bool ovf = (cnt > CAP);            // practically impossible; exact fallback

    // ---- Phase B: 50-iter bisection on warp 0 (identical recursion to ref)
    if (wrp == 0) {
        float tau_lo = max_s - 1.0f;
        const float tau_hi = max_s - 0.005590169943749474f;  // max_s - (1/d)^(alpha-1)
        float dm = tau_hi - tau_lo;
        float tau_m = tau_lo;
        float Z = 1.0f;
        const float* Xrow = X + (size_t)row * COLS;

        #pragma unroll 1
        for (int it = 0; it < 50; it++) {
            dm *= 0.5f;
            tau_m = tau_lo + dm;
            float acc = 0.0f;
            if (!ovf) {
                #pragma unroll 8
                for (int j = lane; j < n; j += 32) {
                    float t = fmaxf(s_vals[j] - tau_m, 0.0f);
                    acc = fmaf(t, t, acc);
                }
            } else {
                for (int j = lane; j < COLS; j += 32) {
                    float t = fmaxf(fmaf(Xrow[j], 0.5f, -tau_m), 0.0f);
                    acc = fmaf(t, t, acc);
                }
            }
            #pragma unroll
            for (int o = 16; o > 0; o >>= 1)
                acc += __shfl_xor_sync(0xFFFFFFFFu, acc, o);
            if (acc - 1.0f >= 0.0f) tau_lo = tau_m;
            Z = acc;   // sum at this iteration's tau_m (matches reference's final p_m)
        }
        if (lane == 0) { s_tau = tau_m; s_invZ = 1.0f / Z; }
    }
    __syncthreads();

    const float tau  = s_tau;
    const float invZ = s_invZ;

    // ---- Phase C: recompute + write full quads (read L2-hot, streaming store)
    for (int i = tid; i < NF4; i += BD) {
        float4 v = Xr[i];
        float4 o; float t;
        t = fmaxf(v.x * 0.5f - tau, 0.0f); o.x = t * t * invZ;
        t = fmaxf(v.y * 0.5f - tau, 0.0f); o.y = t * t * invZ;
        t = fmaxf(v.z * 0.5f - tau, 0.0f); o.z = t * t * invZ;
        t = fmaxf(v.w * 0.5f - tau, 0.0f); o.w = t * t * invZ;
        __stcs(&Or[i], o);
    }
}

// ---------------------------------------------------------------------------
extern "C" void kernel_launch(void* const* d_in, const int* in_sizes, int n_in,
                              void* d_out, int out_size) {
    const float* X = (const float*)d_in[0];
    float* out = (float*)d_out;
    k0_init<<<ROWS / BD, BD>>>();
    k1_rowmax<<<ROWS * SEGS, BD>>>(X);
    k2_entmax<<<ROWS, BD>>>(X, out);
}